// round 5
// baseline (speedup 1.0000x reference)
#include <cuda_runtime.h>

#define BB 8
#define NV 207
#define TT 12
#define LL 2
#define NGH 8
#define ALPHA 0.2f
#define NN (NV*NV)
#define ST 20   // k-major stride for activation buffers (floats)
#define PT 14   // stride for partial-sum buffers

typedef unsigned long long u64t;

// scratch: out buffer (B*N groups, layout per group: e*12+t)
__device__ float g_out[BB*NV*TT*64];

__device__ __forceinline__ float warp_sum(float v){
  #pragma unroll
  for (int o=16;o;o>>=1) v += __shfl_xor_sync(0xffffffffu, v, o);
  return v;
}
__device__ __forceinline__ u64t pack2(float v){
  u64t r; asm("mov.b64 %0, {%1, %1};" : "=l"(r) : "f"(v)); return r;
}
__device__ __forceinline__ void fma2(u64t &acc, u64t a, u64t b){
  asm("fma.rn.f32x2 %0, %1, %2, %0;" : "+l"(acc) : "l"(a), "l"(b));
}

__global__ void k_dummy(){}

// ---------------------------------------------------------------------------
// K1: GAT + conv1. Block = (b, 2-row chunk). Whole x[b] slab staged coalesced.
// ---------------------------------------------------------------------------
__global__ void __launch_bounds__(128) k_gat(
    const float* __restrict__ x,      // (B,C,N,T)
    const int*   __restrict__ adj,    // (B,N,N)
    const float* __restrict__ W2,     // (8,4,2)
    const float* __restrict__ ga,     // (8,2)
    const float* __restrict__ gb,     // (8,2)
    const float* __restrict__ w1,     // (4,64)
    const float* __restrict__ b1)     // (64)
{
  __shared__ float xsa[2*NV*TT];
  __shared__ int   adjs[2*NV];
  __shared__ float w1s[256];
  __shared__ float b1s[64];

  int b  = blockIdx.x;
  int i0 = blockIdx.y * 2;
  int tid = threadIdx.x;

  const float* xb = x + (long)b*2*NV*TT;
  for (int idx=tid; idx<2*NV*TT; idx+=128) xsa[idx] = xb[idx];
  int nrows = (NV - i0) < 2 ? (NV - i0) : 2;
  for (int idx=tid; idx<nrows*NV; idx+=128){
    int ii = idx / NV, j = idx - ii*NV;
    adjs[ii*NV+j] = adj[((long)b*NV + i0+ii)*NV + j];
  }
  for (int idx=tid; idx<256; idx+=128) w1s[idx]=w1[idx];
  if (tid<64) b1s[tid]=b1[tid];
  __syncthreads();

  int warp = tid>>5, lane = tid&31;

  for (int task = warp; task < 24; task += 4){
    int t  = task % 12;
    int ii = task / 12;
    int i  = i0 + ii;
    if (i >= NV) continue;
    const int* arow = adjs + ii*NV;

    float acc0=0.f, acc1=0.f;
    #pragma unroll
    for (int hg=0; hg<2; hg++){
      float w2r[4][4][2], ar[4][2];
      #pragma unroll
      for (int hh=0;hh<4;hh++){
        int h = hg*4+hh;
        #pragma unroll
        for (int k=0;k<4;k++){
          w2r[hh][k][0]=__ldg(W2+(h*4+k)*2+0);
          w2r[hh][k][1]=__ldg(W2+(h*4+k)*2+1);
        }
        ar[hh][0]=__ldg(ga+h*2); ar[hh][1]=__ldg(ga+h*2+1);
      }
      float d[4]={0,0,0,0}, n0[4]={0,0,0,0}, n1[4]={0,0,0,0};
      #pragma unroll
      for (int jj=0; jj<7; jj++){
        int j = jj*32 + lane;
        bool valid = j < NV;
        int jc = valid ? j : 0;
        bool ok = valid && (arow[jc] > 0);
        int r0 = 2*(i*NV + jc);
        int r1 = r0 + 1;
        int a0 = (r0 < NN) ? (r0 / NV) : ((r0 - NN) % NV);
        int a1 = (r1 < NN) ? (r1 / NV) : ((r1 - NN) % NV);
        float cax = xsa[a0*12+t],        cay = xsa[NV*12 + a0*12+t];
        float cbx = xsa[a1*12+t],        cby = xsa[NV*12 + a1*12+t];
        float xjx = xsa[jc*12+t],        xjy = xsa[NV*12 + jc*12+t];
        #pragma unroll
        for (int hh=0;hh<4;hh++){
          float we0 = cax*w2r[hh][0][0] + cay*w2r[hh][1][0] + cbx*w2r[hh][2][0] + cby*w2r[hh][3][0];
          float we1 = cax*w2r[hh][0][1] + cay*w2r[hh][1][1] + cbx*w2r[hh][2][1] + cby*w2r[hh][3][1];
          we0 = (we0 > 0.f) ? we0 : ALPHA*we0;
          we1 = (we1 > 0.f) ? we1 : ALPHA*we1;
          float e = we0*ar[hh][0] + we1*ar[hh][1];
          float w = ok ? __expf(e) : 0.f;
          d[hh]  += w;
          n0[hh] += w*xjx;
          n1[hh] += w*xjy;
        }
      }
      #pragma unroll
      for (int off=16; off; off>>=1){
        #pragma unroll
        for (int hh=0;hh<4;hh++){
          d[hh]  += __shfl_xor_sync(0xffffffffu, d[hh],  off);
          n0[hh] += __shfl_xor_sync(0xffffffffu, n0[hh], off);
          n1[hh] += __shfl_xor_sync(0xffffffffu, n1[hh], off);
        }
      }
      #pragma unroll
      for (int hh=0;hh<4;hh++){
        int h = hg*4+hh;
        float inv = 1.0f/d[hh];
        float z0 = n0[hh]*inv + __ldg(gb+h*2+0);
        float z1 = n1[hh]*inv + __ldg(gb+h*2+1);
        acc0 += 1.f - __fdividef(2.f, __expf(2.f*z0)+1.f);
        acc1 += 1.f - __fdividef(2.f, __expf(2.f*z1)+1.f);
      }
    }
    acc0 *= 0.125f; acc1 *= 0.125f;

    float xi0 = xsa[i*12+t], xi1 = xsa[NV*12 + i*12+t];
    long obase = (long)(b*NV + i)*768;
    #pragma unroll
    for (int r=0;r<2;r++){
      int e = lane + r*32;
      g_out[obase + e*12 + t] = xi0*w1s[e] + xi1*w1s[64+e]
                              + acc0*w1s[128+e] + acc1*w1s[192+e] + b1s[e];
    }
  }
}

// ---------------------------------------------------------------------------
// LayerNorm over e (64) per token; buf k-major stride ST. 4 warps.
// ---------------------------------------------------------------------------
__device__ __forceinline__ void ln_cols(const float* __restrict__ buf,
                                        const float* __restrict__ g,
                                        const float* __restrict__ bvec,
                                        float* __restrict__ dst, int ldd){
  int warp = threadIdx.x>>5, lane = threadIdx.x&31;
  for (int t = warp; t < 12; t += 4){
    float v0 = buf[lane*ST+t], v1 = buf[(lane+32)*ST+t];
    float s  = warp_sum(v0+v1);
    float s2 = warp_sum(v0*v0+v1*v1);
    float mean = s*(1.f/64.f);
    float var  = s2*(1.f/64.f) - mean*mean;
    float r = rsqrtf(var + 1e-5f);
    dst[lane*ldd+t]      = (v0-mean)*r*g[lane]    + bvec[lane];
    dst[(lane+32)*ldd+t] = (v1-mean)*r*g[lane+32] + bvec[lane+32];
  }
}

// ---------------------------------------------------------------------------
// 4-column GEMM: cols (2c2, 2c2+1, coff+2c2, coff+2c2+1).
// Per k: 2x LDG.64 (coalesced) + 3x LDS.128 (broadcast) -> 24 FFMA2.
// ---------------------------------------------------------------------------
__device__ __forceinline__ void gemm4(const float* __restrict__ sIn,
                                      const float* __restrict__ W, int ldw,
                                      int c2, int coff, int k0, int nk,
                                      u64t A0[6], u64t A1[6], u64t A2[6], u64t A3[6]){
  #pragma unroll 2
  for (int k=k0; k<k0+nk; k++){
    const float* wr = W + (long)k*ldw;
    float2 wa = __ldg((const float2*)wr + c2);
    float2 wb = __ldg((const float2*)(wr + coff) + c2);
    u64t b0 = pack2(wa.x), b1 = pack2(wa.y), b2 = pack2(wb.x), b3 = pack2(wb.y);
    const ulonglong2* a = (const ulonglong2*)(sIn + k*ST);
    ulonglong2 v0 = a[0], v1 = a[1], v2 = a[2];
    fma2(A0[0],v0.x,b0); fma2(A1[0],v0.x,b1); fma2(A2[0],v0.x,b2); fma2(A3[0],v0.x,b3);
    fma2(A0[1],v0.y,b0); fma2(A1[1],v0.y,b1); fma2(A2[1],v0.y,b2); fma2(A3[1],v0.y,b3);
    fma2(A0[2],v1.x,b0); fma2(A1[2],v1.x,b1); fma2(A2[2],v1.x,b2); fma2(A3[2],v1.x,b3);
    fma2(A0[3],v1.y,b0); fma2(A1[3],v1.y,b1); fma2(A2[3],v1.y,b2); fma2(A3[3],v1.y,b3);
    fma2(A0[4],v2.x,b0); fma2(A1[4],v2.x,b1); fma2(A2[4],v2.x,b2); fma2(A3[4],v2.x,b3);
    fma2(A0[5],v2.y,b0); fma2(A1[5],v2.y,b1); fma2(A2[5],v2.y,b2); fma2(A3[5],v2.y,b3);
  }
}

__device__ __forceinline__ void store6(float* dst, const u64t A[6]){
  #pragma unroll
  for (int p=0;p<6;p++) ((float2*)dst)[p] = *(const float2*)&A[p];
}

#define ZERO6(A) {A[0]=0;A[1]=0;A[2]=0;A[3]=0;A[4]=0;A[5]=0;}

// ---------------------------------------------------------------------------
// K2: one transformer layer. grid 1656 (=B*N), block 128. smem arena 46KB.
// ---------------------------------------------------------------------------
#define S_QQ 0
#define S_Q  1280
#define S_K  2560
#define S_V  3840
#define S_X1 5120
#define S_H  6400      // 5120 floats
#define SM_TOT 11520

__global__ void __launch_bounds__(128, 4) k_layer(
    const float* __restrict__ temb,
    const float* __restrict__ Wq, const float* __restrict__ Wk,
    const float* __restrict__ Wv, const float* __restrict__ Wo,
    const float* __restrict__ bo,
    const float* __restrict__ ln1g, const float* __restrict__ ln1b,
    const float* __restrict__ ln2g, const float* __restrict__ ln2b,
    const float* __restrict__ fw1, const float* __restrict__ fb1,
    const float* __restrict__ fw2, const float* __restrict__ fb2,
    const float* __restrict__ lng, const float* __restrict__ lnb,
    int l)
{
  __shared__ __align__(16) float sm[SM_TOT];

  int tid = threadIdx.x;
  long base = (long)blockIdx.x * 768;

  const float* Wq_  = Wq  + l*4096;
  const float* Wk_  = Wk  + l*4096;
  const float* Wv_  = Wv  + l*4096;
  const float* Wo_  = Wo  + l*4096;
  const float* bo_  = bo  + l*64;
  const float* ln1g_= ln1g+ l*64;  const float* ln1b_= ln1b+ l*64;
  const float* ln2g_= ln2g+ l*64;  const float* ln2b_= ln2b+ l*64;
  const float* fw1_ = fw1 + l*16384; const float* fb1_ = fb1 + l*256;
  const float* fw2_ = fw2 + l*16384; const float* fb2_ = fb2 + l*64;
  const float* lng_ = lng + l*64;  const float* lnb_ = lnb + l*64;

  for (int idx=tid; idx<768; idx+=128){
    int e = idx/12, t = idx - e*12;
    sm[S_QQ + e*ST+t] = g_out[base+idx] + __ldg(temb + t*64+e);
  }
  __syncthreads();

  // ---- Q,K,V : 48 threads, 4 cols each ----
  if (tid < 48){
    int g = tid >> 4, c2 = tid & 15;
    const float* W = (g==0 ? Wq_ : (g==1 ? Wk_ : Wv_));
    float* dst = sm + (g==0 ? S_Q : (g==1 ? S_K : S_V));
    u64t A0[6],A1[6],A2[6],A3[6]; ZERO6(A0) ZERO6(A1) ZERO6(A2) ZERO6(A3)
    gemm4(sm + S_QQ, W, 64, c2, 32, 0, 64, A0,A1,A2,A3);
    store6(dst + (2*c2)*ST,    A0);
    store6(dst + (2*c2+1)*ST,  A1);
    store6(dst + (2*c2+32)*ST, A2);
    store6(dst + (2*c2+33)*ST, A3);
  }
  __syncthreads();

  // ---- attention scores (into S_H) ----
  for (int idx=tid; idx<576; idx+=128){
    int h = idx/144, rem = idx - h*144;
    int t2 = rem/12, s = rem - t2*12;
    const float* qp = sm + S_Q + (h*16)*ST + t2;
    const float* kp = sm + S_K + (h*16)*ST + s;
    float sum=0.f;
    #pragma unroll
    for (int dd=0;dd<16;dd++) sum += qp[dd*ST]*kp[dd*ST];
    sm[S_H + idx] = sum*0.25f;
  }
  __syncthreads();
  if (tid < 48){
    float* row = sm + S_H + tid*12;
    float mxv = row[0];
    #pragma unroll
    for (int s=1;s<12;s++) mxv = fmaxf(mxv,row[s]);
    float evv[12]; float sum=0.f;
    #pragma unroll
    for (int s=0;s<12;s++){ evv[s]=__expf(row[s]-mxv); sum+=evv[s]; }
    float inv = 1.f/sum;
    #pragma unroll
    for (int s=0;s<12;s++) row[s]=evv[s]*inv;
  }
  __syncthreads();

  // ---- ctx = att @ V (into S_Q; Q dead) ----
  for (int idx=tid; idx<768; idx+=128){
    int e = idx/12, t2 = idx - e*12, h = e>>4;
    const float* a = sm + S_H + (h*12+t2)*12;
    const float* vp = sm + S_V + e*ST;
    float sum=0.f;
    #pragma unroll
    for (int s=0;s<12;s++) sum += a[s]*vp[s];
    sm[S_Q + e*ST+t2] = sum;
  }
  __syncthreads();

  // ---- attn_out = ctx @ Wo : 32 threads, 2 k-groups, 4 cols ----
  if (tid < 32){
    int kg = tid>>4, c2 = tid&15;
    u64t A0[6],A1[6],A2[6],A3[6]; ZERO6(A0) ZERO6(A1) ZERO6(A2) ZERO6(A3)
    gemm4(sm + S_Q, Wo_, 64, c2, 32, kg*32, 32, A0,A1,A2,A3);
    float* pb = sm + S_H + kg*896;
    store6(pb + (2*c2)*PT,    A0);
    store6(pb + (2*c2+1)*PT,  A1);
    store6(pb + (2*c2+32)*PT, A2);
    store6(pb + (2*c2+33)*PT, A3);
  }
  __syncthreads();
  for (int idx=tid; idx<768; idx+=128){
    int e = idx/12, t2 = idx - e*12, p = e*PT + t2;
    sm[S_X1 + e*ST+t2] = sm[S_H+p]+sm[S_H+896+p]
                       + bo_[e] + sm[S_QQ + e*ST+t2];
  }
  __syncthreads();
  ln_cols(sm+S_X1, ln1g_, ln1b_, sm+S_X1, ST);
  __syncthreads();

  // ---- FF1: 64 threads, 4 cols each (2f,2f+1,2f+128,2f+129), k=64 ----
  if (tid < 64){
    int f = tid;
    u64t A0[6],A1[6],A2[6],A3[6]; ZERO6(A0) ZERO6(A1) ZERO6(A2) ZERO6(A3)
    gemm4(sm + S_X1, fw1_, 256, f, 128, 0, 64, A0,A1,A2,A3);
    float b0 = fb1_[2*f], b1v = fb1_[2*f+1], b2v = fb1_[2*f+128], b3v = fb1_[2*f+129];
    u64t* accs[4] = {A0,A1,A2,A3};
    float bs[4] = {b0,b1v,b2v,b3v};
    int cols[4] = {2*f, 2*f+1, 2*f+128, 2*f+129};
    #pragma unroll
    for (int q=0;q<4;q++){
      float* d = sm + S_H + cols[q]*ST;
      #pragma unroll
      for (int p=0;p<6;p++){
        float2 v = *(const float2*)&accs[q][p];
        v.x = fmaxf(v.x+bs[q],0.f); v.y = fmaxf(v.y+bs[q],0.f);
        ((float2*)d)[p] = v;
      }
    }
  }
  __syncthreads();

  // ---- FF2: 64 threads, 4 k-groups of 64, 4 cols; partials at S_Q ----
  {
    int kg = tid>>4, c2 = tid&15;
    u64t A0[6],A1[6],A2[6],A3[6]; ZERO6(A0) ZERO6(A1) ZERO6(A2) ZERO6(A3)
    if (tid < 64){
      gemm4(sm + S_H, fw2_, 64, c2, 32, kg*64, 64, A0,A1,A2,A3);
      float* pb = sm + S_Q + kg*896;
      store6(pb + (2*c2)*PT,    A0);
      store6(pb + (2*c2+1)*PT,  A1);
      store6(pb + (2*c2+32)*PT, A2);
      store6(pb + (2*c2+33)*PT, A3);
    }
  }
  __syncthreads();
  for (int idx=tid; idx<768; idx+=128){
    int e = idx/12, t2 = idx - e*12, p = S_Q + e*PT + t2, o = S_X1 + e*ST+t2;
    sm[o] = sm[p]+sm[p+896]+sm[p+1792]+sm[p+2688] + fb2_[e] + sm[o];
  }
  __syncthreads();
  ln_cols(sm+S_X1, ln2g_, ln2b_, sm+S_X1, ST);
  __syncthreads();
  for (int idx=tid; idx<768; idx+=128){
    int e = idx/12, t2 = idx - e*12;
    sm[S_H + e*ST+t2] = sm[S_X1 + e*ST+t2] + sm[S_QQ + e*ST+t2] - __ldg(temb + t2*64+e);
  }
  __syncthreads();
  ln_cols(sm+S_H, lng_, lnb_, g_out + base, 12);
}

// ---------------------------------------------------------------------------
// K3: conv2 + relu + conv3 head. One warp per (b,n).
// ---------------------------------------------------------------------------
__global__ void __launch_bounds__(128) k_final(
    const float* __restrict__ w2, const float* __restrict__ b2,
    const float* __restrict__ w3, const float* __restrict__ b3,
    float* __restrict__ outp)
{
  int id = blockIdx.x*4 + (threadIdx.x>>5);
  if (id >= BB*NV) return;
  int lane = threadIdx.x & 31;
  const float* row = g_out + (long)id*768;
  float o0[12], o1[12];
  {
    const float4* r4 = (const float4*)(row + lane*12);
    float4 a0=r4[0], a1=r4[1], a2=r4[2];
    o0[0]=a0.x;o0[1]=a0.y;o0[2]=a0.z;o0[3]=a0.w;
    o0[4]=a1.x;o0[5]=a1.y;o0[6]=a1.z;o0[7]=a1.w;
    o0[8]=a2.x;o0[9]=a2.y;o0[10]=a2.z;o0[11]=a2.w;
    const float4* s4 = (const float4*)(row + (lane+32)*12);
    float4 c0=s4[0], c1=s4[1], c2=s4[2];
    o1[0]=c0.x;o1[1]=c0.y;o1[2]=c0.z;o1[3]=c0.w;
    o1[4]=c1.x;o1[5]=c1.y;o1[6]=c1.z;o1[7]=c1.w;
    o1[8]=c2.x;o1[9]=c2.y;o1[10]=c2.z;o1[11]=c2.w;
  }
  float w3a = w3[lane], w3b = w3[lane+32];
  float b3v = b3[0];
  #pragma unroll
  for (int o=0;o<12;o++){
    float v0 = b2[o], v1 = b2[o];
    #pragma unroll
    for (int t=0;t<12;t++){ float w = w2[o*12+t]; v0 += o0[t]*w; v1 += o1[t]*w; }
    v0 = fmaxf(v0,0.f); v1 = fmaxf(v1,0.f);
    float p = warp_sum(v0*w3a + v1*w3b);
    if (lane==0) outp[id*12+o] = p + b3v;
  }
}

// ---------------------------------------------------------------------------
extern "C" void kernel_launch(void* const* d_in, const int* in_sizes, int n_in,
                              void* d_out, int out_size) {
  const float* x       = (const float*)d_in[0];
  const int*   adj     = (const int*)  d_in[1];
  const float* gat_W2  = (const float*)d_in[2];
  const float* gat_a   = (const float*)d_in[3];
  const float* gat_b   = (const float*)d_in[4];
  const float* conv1_w = (const float*)d_in[5];
  const float* conv1_b = (const float*)d_in[6];
  const float* temb    = (const float*)d_in[7];
  const float* Wq      = (const float*)d_in[8];
  const float* Wk      = (const float*)d_in[9];
  const float* Wv      = (const float*)d_in[10];
  const float* Wo      = (const float*)d_in[11];
  const float* bo      = (const float*)d_in[12];
  const float* ln1_g   = (const float*)d_in[13];
  const float* ln1_b   = (const float*)d_in[14];
  const float* ln2_g   = (const float*)d_in[15];
  const float* ln2_b   = (const float*)d_in[16];
  const float* ff_w1   = (const float*)d_in[17];
  const float* ff_b1   = (const float*)d_in[18];
  const float* ff_w2   = (const float*)d_in[19];
  const float* ff_b2   = (const float*)d_in[20];
  const float* lng     = (const float*)d_in[21];
  const float* lnb     = (const float*)d_in[22];
  const float* conv2_w = (const float*)d_in[23];
  const float* conv2_b = (const float*)d_in[24];
  const float* conv3_w = (const float*)d_in[25];
  const float* conv3_b = (const float*)d_in[26];
  float* outp = (float*)d_out;

  // dummy first: keeps ncu's fixed capture index on k_layer
  k_dummy<<<1, 32>>>();

  dim3 g1(BB, (NV + 1) / 2);
  k_gat<<<g1, 128>>>(x, adj, gat_W2, gat_a, gat_b, conv1_w, conv1_b);

  for (int l = 0; l < LL; l++) {
    k_layer<<<BB*NV, 128>>>(temb, Wq, Wk, Wv, Wo, bo,
                            ln1_g, ln1_b, ln2_g, ln2_b,
                            ff_w1, ff_b1, ff_w2, ff_b2,
                            lng, lnb, l);
  }

  k_final<<<(BB*NV + 3)/4, 128>>>(conv2_w, conv2_b, conv3_w, conv3_b, outp);
}

// round 6
// speedup vs baseline: 1.2812x; 1.2812x over previous
#include <cuda_runtime.h>

#define BB 8
#define NV 207
#define TT 12
#define LL 2
#define NGH 8
#define ALPHA 0.2f
#define NN (NV*NV)
#define ST 20   // k-major stride for activation buffers (floats)
#define PT 14   // stride for partial-sum buffers

typedef unsigned long long u64t;

// scratch: gat output (B*N groups, layout per group: e*12+t)
__device__ float g_out[BB*NV*TT*64];

__device__ __forceinline__ float warp_sum(float v){
  #pragma unroll
  for (int o=16;o;o>>=1) v += __shfl_xor_sync(0xffffffffu, v, o);
  return v;
}
__device__ __forceinline__ u64t pack2(float v){
  u64t r; asm("mov.b64 %0, {%1, %1};" : "=l"(r) : "f"(v)); return r;
}
__device__ __forceinline__ void fma2(u64t &acc, u64t a, u64t b){
  asm("fma.rn.f32x2 %0, %1, %2, %0;" : "+l"(acc) : "l"(a), "l"(b));
}

__global__ void k_dummy(){}

// ---------------------------------------------------------------------------
// K1: GAT + conv1. Block = (b, 2-row chunk). Whole x[b] slab staged coalesced.
// ---------------------------------------------------------------------------
__global__ void __launch_bounds__(128) k_gat(
    const float* __restrict__ x,      // (B,C,N,T)
    const int*   __restrict__ adj,    // (B,N,N)
    const float* __restrict__ W2,     // (8,4,2)
    const float* __restrict__ ga,     // (8,2)
    const float* __restrict__ gb,     // (8,2)
    const float* __restrict__ w1,     // (4,64)
    const float* __restrict__ b1)     // (64)
{
  __shared__ float xsa[2*NV*TT];
  __shared__ int   adjs[2*NV];
  __shared__ float w1s[256];
  __shared__ float b1s[64];

  int b  = blockIdx.x;
  int i0 = blockIdx.y * 2;
  int tid = threadIdx.x;

  const float* xb = x + (long)b*2*NV*TT;
  for (int idx=tid; idx<2*NV*TT; idx+=128) xsa[idx] = xb[idx];
  int nrows = (NV - i0) < 2 ? (NV - i0) : 2;
  for (int idx=tid; idx<nrows*NV; idx+=128){
    int ii = idx / NV, j = idx - ii*NV;
    adjs[ii*NV+j] = adj[((long)b*NV + i0+ii)*NV + j];
  }
  for (int idx=tid; idx<256; idx+=128) w1s[idx]=w1[idx];
  if (tid<64) b1s[tid]=b1[tid];
  __syncthreads();

  int warp = tid>>5, lane = tid&31;

  for (int task = warp; task < 24; task += 4){
    int t  = task % 12;
    int ii = task / 12;
    int i  = i0 + ii;
    if (i >= NV) continue;
    const int* arow = adjs + ii*NV;

    float acc0=0.f, acc1=0.f;
    #pragma unroll
    for (int hg=0; hg<2; hg++){
      float w2r[4][4][2], ar[4][2];
      #pragma unroll
      for (int hh=0;hh<4;hh++){
        int h = hg*4+hh;
        #pragma unroll
        for (int k=0;k<4;k++){
          w2r[hh][k][0]=__ldg(W2+(h*4+k)*2+0);
          w2r[hh][k][1]=__ldg(W2+(h*4+k)*2+1);
        }
        ar[hh][0]=__ldg(ga+h*2); ar[hh][1]=__ldg(ga+h*2+1);
      }
      float d[4]={0,0,0,0}, n0[4]={0,0,0,0}, n1[4]={0,0,0,0};
      #pragma unroll
      for (int jj=0; jj<7; jj++){
        int j = jj*32 + lane;
        bool valid = j < NV;
        int jc = valid ? j : 0;
        bool ok = valid && (arow[jc] > 0);
        int r0 = 2*(i*NV + jc);
        int r1 = r0 + 1;
        int a0 = (r0 < NN) ? (r0 / NV) : ((r0 - NN) % NV);
        int a1 = (r1 < NN) ? (r1 / NV) : ((r1 - NN) % NV);
        float cax = xsa[a0*12+t],        cay = xsa[NV*12 + a0*12+t];
        float cbx = xsa[a1*12+t],        cby = xsa[NV*12 + a1*12+t];
        float xjx = xsa[jc*12+t],        xjy = xsa[NV*12 + jc*12+t];
        #pragma unroll
        for (int hh=0;hh<4;hh++){
          float we0 = cax*w2r[hh][0][0] + cay*w2r[hh][1][0] + cbx*w2r[hh][2][0] + cby*w2r[hh][3][0];
          float we1 = cax*w2r[hh][0][1] + cay*w2r[hh][1][1] + cbx*w2r[hh][2][1] + cby*w2r[hh][3][1];
          we0 = (we0 > 0.f) ? we0 : ALPHA*we0;
          we1 = (we1 > 0.f) ? we1 : ALPHA*we1;
          float e = we0*ar[hh][0] + we1*ar[hh][1];
          float w = ok ? __expf(e) : 0.f;
          d[hh]  += w;
          n0[hh] += w*xjx;
          n1[hh] += w*xjy;
        }
      }
      #pragma unroll
      for (int off=16; off; off>>=1){
        #pragma unroll
        for (int hh=0;hh<4;hh++){
          d[hh]  += __shfl_xor_sync(0xffffffffu, d[hh],  off);
          n0[hh] += __shfl_xor_sync(0xffffffffu, n0[hh], off);
          n1[hh] += __shfl_xor_sync(0xffffffffu, n1[hh], off);
        }
      }
      #pragma unroll
      for (int hh=0;hh<4;hh++){
        int h = hg*4+hh;
        float inv = 1.0f/d[hh];
        float z0 = n0[hh]*inv + __ldg(gb+h*2+0);
        float z1 = n1[hh]*inv + __ldg(gb+h*2+1);
        acc0 += 1.f - __fdividef(2.f, __expf(2.f*z0)+1.f);
        acc1 += 1.f - __fdividef(2.f, __expf(2.f*z1)+1.f);
      }
    }
    acc0 *= 0.125f; acc1 *= 0.125f;

    float xi0 = xsa[i*12+t], xi1 = xsa[NV*12 + i*12+t];
    long obase = (long)(b*NV + i)*768;
    #pragma unroll
    for (int r=0;r<2;r++){
      int e = lane + r*32;
      g_out[obase + e*12 + t] = xi0*w1s[e] + xi1*w1s[64+e]
                              + acc0*w1s[128+e] + acc1*w1s[192+e] + b1s[e];
    }
  }
}

// ---------------------------------------------------------------------------
// LayerNorm over e (64) per token; 8 warps (256-thread block).
// ---------------------------------------------------------------------------
__device__ __forceinline__ void ln_cols(const float* __restrict__ buf,
                                        const float* __restrict__ g,
                                        const float* __restrict__ bvec,
                                        float* __restrict__ dst, int ldd){
  int warp = threadIdx.x>>5, lane = threadIdx.x&31;
  for (int t = warp; t < 12; t += 8){
    float v0 = buf[lane*ST+t], v1 = buf[(lane+32)*ST+t];
    float s  = warp_sum(v0+v1);
    float s2 = warp_sum(v0*v0+v1*v1);
    float mean = s*(1.f/64.f);
    float var  = s2*(1.f/64.f) - mean*mean;
    float r = rsqrtf(var + 1e-5f);
    dst[lane*ldd+t]      = (v0-mean)*r*g[lane]    + bvec[lane];
    dst[(lane+32)*ldd+t] = (v1-mean)*r*g[lane+32] + bvec[lane+32];
  }
}

// 2-column GEMM: columns c0, c1 far apart; 12 tokens in 6 f32x2 accumulators.
__device__ __forceinline__ void gemm2(const float* __restrict__ sIn,
                                      const float* __restrict__ W, int ldw,
                                      int c0, int c1, int k0, int nk,
                                      u64t A[6], u64t Bc[6]){
  #pragma unroll 4
  for (int k=k0; k<k0+nk; k++){
    const float* wr = W + (long)k*ldw;
    u64t wa = pack2(__ldg(wr+c0));
    u64t wb = pack2(__ldg(wr+c1));
    const ulonglong2* a = (const ulonglong2*)(sIn + k*ST);
    ulonglong2 v0 = a[0], v1 = a[1], v2 = a[2];
    fma2(A[0], v0.x, wa); fma2(Bc[0], v0.x, wb);
    fma2(A[1], v0.y, wa); fma2(Bc[1], v0.y, wb);
    fma2(A[2], v1.x, wa); fma2(Bc[2], v1.x, wb);
    fma2(A[3], v1.y, wa); fma2(Bc[3], v1.y, wb);
    fma2(A[4], v2.x, wa); fma2(Bc[4], v2.x, wb);
    fma2(A[5], v2.y, wa); fma2(Bc[5], v2.y, wb);
  }
}

__device__ __forceinline__ void store6(float* dst, const u64t A[6]){
  #pragma unroll
  for (int p=0;p<6;p++) ((float2*)dst)[p] = *(const float2*)&A[p];
}

// ---------------------------------------------------------------------------
// K2: BOTH transformer layers + conv2/conv3 head fused.
// grid 1656 (=B*N), block 256. smem arena 45KB. Activations never leave smem.
// ---------------------------------------------------------------------------
#define S_QQ 0
#define S_Q  1280
#define S_K  2560
#define S_V  3840
#define S_X1 5120
#define S_H  6400      // 5120 floats
#define SM_TOT 11520

__global__ void __launch_bounds__(256, 4) k_fused(
    const float* __restrict__ temb,
    const float* __restrict__ Wq, const float* __restrict__ Wk,
    const float* __restrict__ Wv, const float* __restrict__ Wo,
    const float* __restrict__ bo,
    const float* __restrict__ ln1g, const float* __restrict__ ln1b,
    const float* __restrict__ ln2g, const float* __restrict__ ln2b,
    const float* __restrict__ fw1, const float* __restrict__ fb1,
    const float* __restrict__ fw2, const float* __restrict__ fb2,
    const float* __restrict__ lng, const float* __restrict__ lnb,
    const float* __restrict__ w2c, const float* __restrict__ b2c,
    const float* __restrict__ w3c, const float* __restrict__ b3c,
    float* __restrict__ outp)
{
  __shared__ __align__(16) float sm[SM_TOT];

  int tid = threadIdx.x;
  long base = (long)blockIdx.x * 768;

  for (int idx=tid; idx<768; idx+=256){
    int e = idx/12, t = idx - e*12;
    sm[S_QQ + e*ST+t] = g_out[base+idx] + __ldg(temb + t*64+e);
  }
  __syncthreads();

  for (int l=0; l<LL; l++){
    const float* Wq_  = Wq  + l*4096;
    const float* Wk_  = Wk  + l*4096;
    const float* Wv_  = Wv  + l*4096;
    const float* Wo_  = Wo  + l*4096;
    const float* bo_  = bo  + l*64;
    const float* ln1g_= ln1g+ l*64;  const float* ln1b_= ln1b+ l*64;
    const float* ln2g_= ln2g+ l*64;  const float* ln2b_= ln2b+ l*64;
    const float* fw1_ = fw1 + l*16384; const float* fb1_ = fb1 + l*256;
    const float* fw2_ = fw2 + l*16384; const float* fb2_ = fb2 + l*64;
    const float* lng_ = lng + l*64;  const float* lnb_ = lnb + l*64;

    // ---- Q,K,V : 96 threads, cols (e2, e2+32) ----
    if (tid < 96){
      int g = tid >> 5, e2 = tid & 31;
      const float* W = (g==0 ? Wq_ : (g==1 ? Wk_ : Wv_));
      float* dst = sm + (g==0 ? S_Q : (g==1 ? S_K : S_V));
      u64t A[6]={0,0,0,0,0,0}, B[6]={0,0,0,0,0,0};
      gemm2(sm + S_QQ, W, 64, e2, e2+32, 0, 64, A, B);
      store6(dst + e2*ST, A);
      store6(dst + (e2+32)*ST, B);
    }
    __syncthreads();

    // ---- attention scores (into S_H) ----
    for (int idx=tid; idx<576; idx+=256){
      int h = idx/144, rem = idx - h*144;
      int t2 = rem/12, s = rem - t2*12;
      const float* qp = sm + S_Q + (h*16)*ST + t2;
      const float* kp = sm + S_K + (h*16)*ST + s;
      float sum=0.f;
      #pragma unroll
      for (int dd=0;dd<16;dd++) sum += qp[dd*ST]*kp[dd*ST];
      sm[S_H + idx] = sum*0.25f;
    }
    __syncthreads();
    if (tid < 48){
      float* row = sm + S_H + tid*12;
      float mxv = row[0];
      #pragma unroll
      for (int s=1;s<12;s++) mxv = fmaxf(mxv,row[s]);
      float evv[12]; float sum=0.f;
      #pragma unroll
      for (int s=0;s<12;s++){ evv[s]=__expf(row[s]-mxv); sum+=evv[s]; }
      float inv = 1.f/sum;
      #pragma unroll
      for (int s=0;s<12;s++) row[s]=evv[s]*inv;
    }
    __syncthreads();

    // ---- ctx = att @ V (into S_Q; Q dead) ----
    for (int idx=tid; idx<768; idx+=256){
      int e = idx/12, t2 = idx - e*12, h = e>>4;
      const float* a = sm + S_H + (h*12+t2)*12;
      const float* vp = sm + S_V + e*ST;
      float sum=0.f;
      #pragma unroll
      for (int s=0;s<12;s++) sum += a[s]*vp[s];
      sm[S_Q + e*ST+t2] = sum;
    }
    __syncthreads();

    // ---- attn_out = ctx @ Wo : 128 threads, 4 k-groups, cols (e2,e2+32) ----
    if (tid < 128){
      int kg = tid>>5, e2 = tid&31;
      u64t A[6]={0,0,0,0,0,0}, B[6]={0,0,0,0,0,0};
      gemm2(sm + S_Q, Wo_, 64, e2, e2+32, kg*16, 16, A, B);
      float* pb = sm + S_H + kg*896;
      store6(pb + e2*PT, A);
      store6(pb + (e2+32)*PT, B);
    }
    __syncthreads();
    for (int idx=tid; idx<768; idx+=256){
      int e = idx/12, t2 = idx - e*12, p = e*PT + t2;
      sm[S_X1 + e*ST+t2] = sm[S_H+p]+sm[S_H+896+p]+sm[S_H+1792+p]+sm[S_H+2688+p]
                         + bo_[e] + sm[S_QQ + e*ST+t2];
    }
    __syncthreads();
    ln_cols(sm+S_X1, ln1g_, ln1b_, sm+S_X1, ST);
    __syncthreads();

    // ---- FF1: 128 threads, cols (f, f+128), k=64 ----
    if (tid < 128){
      int f = tid;
      u64t A[6]={0,0,0,0,0,0}, B[6]={0,0,0,0,0,0};
      gemm2(sm + S_X1, fw1_, 256, f, f+128, 0, 64, A, B);
      float ba = fb1_[f], bb2 = fb1_[f+128];
      float* dA = sm + S_H + f*ST;
      float* dB = sm + S_H + (f+128)*ST;
      #pragma unroll
      for (int p=0;p<6;p++){
        float2 va = *(const float2*)&A[p];
        float2 vb = *(const float2*)&B[p];
        va.x = fmaxf(va.x+ba,0.f);  va.y = fmaxf(va.y+ba,0.f);
        vb.x = fmaxf(vb.x+bb2,0.f); vb.y = fmaxf(vb.y+bb2,0.f);
        ((float2*)dA)[p] = va;
        ((float2*)dB)[p] = vb;
      }
    }
    __syncthreads();

    // ---- FF2: 128 threads, 4 k-groups of 64, cols (e2,e2+32); partials at S_Q ----
    if (tid < 128){
      int kg = tid>>5, e2 = tid&31;
      u64t A[6]={0,0,0,0,0,0}, B[6]={0,0,0,0,0,0};
      gemm2(sm + S_H, fw2_, 64, e2, e2+32, kg*64, 64, A, B);
      float* pb = sm + S_Q + kg*896;
      store6(pb + e2*PT, A);
      store6(pb + (e2+32)*PT, B);
    }
    __syncthreads();
    for (int idx=tid; idx<768; idx+=256){
      int e = idx/12, t2 = idx - e*12, p = S_Q + e*PT + t2, o = S_X1 + e*ST+t2;
      sm[o] = sm[p]+sm[p+896]+sm[p+1792]+sm[p+2688] + fb2_[e] + sm[o];
    }
    __syncthreads();
    ln_cols(sm+S_X1, ln2g_, ln2b_, sm+S_X1, ST);
    __syncthreads();
    // blk + out_prev (= QQ - temb)
    for (int idx=tid; idx<768; idx+=256){
      int e = idx/12, t2 = idx - e*12;
      sm[S_H + e*ST+t2] = sm[S_X1 + e*ST+t2] + sm[S_QQ + e*ST+t2] - __ldg(temb + t2*64+e);
    }
    __syncthreads();
    ln_cols(sm+S_H, lng_, lnb_, sm+S_K, ST);    // layer output -> S_K
    __syncthreads();
    if (l+1 < LL){
      for (int idx=tid; idx<768; idx+=256){
        int e = idx/12, t2 = idx - e*12;
        sm[S_QQ + e*ST+t2] = sm[S_K + e*ST+t2] + __ldg(temb + t2*64+e);
      }
      __syncthreads();
    }
  }

  // ---- head: conv2 over t (relu) + conv3 over e. out in S_K ----
  if (tid < 192){
    int o = tid>>4, es = (tid&15)*4;
    float w2row[12];
    #pragma unroll
    for (int t=0;t<12;t++) w2row[t] = __ldg(w2c + o*12 + t);
    float b2v = __ldg(b2c + o);
    float acc = 0.f;
    #pragma unroll
    for (int q=0;q<4;q++){
      int e = es + q;
      const float* rowp = sm + S_K + e*ST;
      float v = b2v;
      #pragma unroll
      for (int t=0;t<12;t++) v += rowp[t]*w2row[t];
      v = fmaxf(v, 0.f);
      acc += v * __ldg(w3c + e);
    }
    #pragma unroll
    for (int off=8; off; off>>=1) acc += __shfl_xor_sync(0xffffffffu, acc, off);
    if ((tid&15)==0) outp[(long)blockIdx.x*12 + o] = acc + __ldg(b3c);
  }
}

// ---------------------------------------------------------------------------
extern "C" void kernel_launch(void* const* d_in, const int* in_sizes, int n_in,
                              void* d_out, int out_size) {
  const float* x       = (const float*)d_in[0];
  const int*   adj     = (const int*)  d_in[1];
  const float* gat_W2  = (const float*)d_in[2];
  const float* gat_a   = (const float*)d_in[3];
  const float* gat_b   = (const float*)d_in[4];
  const float* conv1_w = (const float*)d_in[5];
  const float* conv1_b = (const float*)d_in[6];
  const float* temb    = (const float*)d_in[7];
  const float* Wq      = (const float*)d_in[8];
  const float* Wk      = (const float*)d_in[9];
  const float* Wv      = (const float*)d_in[10];
  const float* Wo      = (const float*)d_in[11];
  const float* bo      = (const float*)d_in[12];
  const float* ln1_g   = (const float*)d_in[13];
  const float* ln1_b   = (const float*)d_in[14];
  const float* ln2_g   = (const float*)d_in[15];
  const float* ln2_b   = (const float*)d_in[16];
  const float* ff_w1   = (const float*)d_in[17];
  const float* ff_b1   = (const float*)d_in[18];
  const float* ff_w2   = (const float*)d_in[19];
  const float* ff_b2   = (const float*)d_in[20];
  const float* lng     = (const float*)d_in[21];
  const float* lnb     = (const float*)d_in[22];
  const float* conv2_w = (const float*)d_in[23];
  const float* conv2_b = (const float*)d_in[24];
  const float* conv3_w = (const float*)d_in[25];
  const float* conv3_b = (const float*)d_in[26];
  float* outp = (float*)d_out;

  // dummy first: keeps ncu's fixed capture index aligned
  k_dummy<<<1, 32>>>();

  dim3 g1(BB, (NV + 1) / 2);
  k_gat<<<g1, 128>>>(x, adj, gat_W2, gat_a, gat_b, conv1_w, conv1_b);

  k_fused<<<BB*NV, 256>>>(temb, Wq, Wk, Wv, Wo, bo,
                          ln1_g, ln1_b, ln2_g, ln2_b,
                          ff_w1, ff_b1, ff_w2, ff_b2,
                          lng, lnb,
                          conv2_w, conv2_b, conv3_w, conv3_b, outp);
}

// round 7
// speedup vs baseline: 1.3261x; 1.0351x over previous
#include <cuda_runtime.h>

#define BB 8
#define NV 207
#define TT 12
#define LL 2
#define NGH 8
#define ALPHA 0.2f
#define NN (NV*NV)
#define ST 20   // k-major stride for activation buffers (floats)
#define PT 14   // stride for partial-sum buffers

typedef unsigned long long u64t;

// scratch: gat output (B*N groups, layout per group: e*12+t)
__device__ float g_out[BB*NV*TT*64];

__device__ __forceinline__ float warp_sum(float v){
  #pragma unroll
  for (int o=16;o;o>>=1) v += __shfl_xor_sync(0xffffffffu, v, o);
  return v;
}
__device__ __forceinline__ u64t pack2(float v){
  u64t r; asm("mov.b64 %0, {%1, %1};" : "=l"(r) : "f"(v)); return r;
}
__device__ __forceinline__ void fma2(u64t &acc, u64t a, u64t b){
  asm("fma.rn.f32x2 %0, %1, %2, %0;" : "+l"(acc) : "l"(a), "l"(b));
}

// ---------------------------------------------------------------------------
// K1: GAT + conv1. Block = (b, 2-row chunk). Whole x[b] slab staged coalesced.
// ---------------------------------------------------------------------------
__global__ void __launch_bounds__(128) k_gat(
    const float* __restrict__ x,      // (B,C,N,T)
    const int*   __restrict__ adj,    // (B,N,N)
    const float* __restrict__ W2,     // (8,4,2)
    const float* __restrict__ ga,     // (8,2)
    const float* __restrict__ gb,     // (8,2)
    const float* __restrict__ w1,     // (4,64)
    const float* __restrict__ b1)     // (64)
{
  __shared__ float xsa[2*NV*TT];
  __shared__ int   adjs[2*NV];
  __shared__ float w1s[256];
  __shared__ float b1s[64];

  int b  = blockIdx.x;
  int i0 = blockIdx.y * 2;
  int tid = threadIdx.x;

  const float* xb = x + (long)b*2*NV*TT;
  for (int idx=tid; idx<2*NV*TT; idx+=128) xsa[idx] = xb[idx];
  int nrows = (NV - i0) < 2 ? (NV - i0) : 2;
  for (int idx=tid; idx<nrows*NV; idx+=128){
    int ii = idx / NV, j = idx - ii*NV;
    adjs[ii*NV+j] = adj[((long)b*NV + i0+ii)*NV + j];
  }
  for (int idx=tid; idx<256; idx+=128) w1s[idx]=w1[idx];
  if (tid<64) b1s[tid]=b1[tid];
  __syncthreads();

  int warp = tid>>5, lane = tid&31;

  for (int task = warp; task < 24; task += 4){
    int t  = task % 12;
    int ii = task / 12;
    int i  = i0 + ii;
    if (i >= NV) continue;
    const int* arow = adjs + ii*NV;

    float acc0=0.f, acc1=0.f;
    #pragma unroll
    for (int hg=0; hg<2; hg++){
      float w2r[4][4][2], ar[4][2];
      #pragma unroll
      for (int hh=0;hh<4;hh++){
        int h = hg*4+hh;
        #pragma unroll
        for (int k=0;k<4;k++){
          w2r[hh][k][0]=__ldg(W2+(h*4+k)*2+0);
          w2r[hh][k][1]=__ldg(W2+(h*4+k)*2+1);
        }
        ar[hh][0]=__ldg(ga+h*2); ar[hh][1]=__ldg(ga+h*2+1);
      }
      float d[4]={0,0,0,0}, n0[4]={0,0,0,0}, n1[4]={0,0,0,0};
      #pragma unroll
      for (int jj=0; jj<7; jj++){
        int j = jj*32 + lane;
        bool valid = j < NV;
        int jc = valid ? j : 0;
        bool ok = valid && (arow[jc] > 0);
        int r0 = 2*(i*NV + jc);
        int r1 = r0 + 1;
        int a0 = (r0 < NN) ? (r0 / NV) : ((r0 - NN) % NV);
        int a1 = (r1 < NN) ? (r1 / NV) : ((r1 - NN) % NV);
        float cax = xsa[a0*12+t],        cay = xsa[NV*12 + a0*12+t];
        float cbx = xsa[a1*12+t],        cby = xsa[NV*12 + a1*12+t];
        float xjx = xsa[jc*12+t],        xjy = xsa[NV*12 + jc*12+t];
        #pragma unroll
        for (int hh=0;hh<4;hh++){
          float we0 = cax*w2r[hh][0][0] + cay*w2r[hh][1][0] + cbx*w2r[hh][2][0] + cby*w2r[hh][3][0];
          float we1 = cax*w2r[hh][0][1] + cay*w2r[hh][1][1] + cbx*w2r[hh][2][1] + cby*w2r[hh][3][1];
          we0 = (we0 > 0.f) ? we0 : ALPHA*we0;
          we1 = (we1 > 0.f) ? we1 : ALPHA*we1;
          float e = we0*ar[hh][0] + we1*ar[hh][1];
          float w = ok ? __expf(e) : 0.f;
          d[hh]  += w;
          n0[hh] += w*xjx;
          n1[hh] += w*xjy;
        }
      }
      #pragma unroll
      for (int off=16; off; off>>=1){
        #pragma unroll
        for (int hh=0;hh<4;hh++){
          d[hh]  += __shfl_xor_sync(0xffffffffu, d[hh],  off);
          n0[hh] += __shfl_xor_sync(0xffffffffu, n0[hh], off);
          n1[hh] += __shfl_xor_sync(0xffffffffu, n1[hh], off);
        }
      }
      #pragma unroll
      for (int hh=0;hh<4;hh++){
        int h = hg*4+hh;
        float inv = 1.0f/d[hh];
        float z0 = n0[hh]*inv + __ldg(gb+h*2+0);
        float z1 = n1[hh]*inv + __ldg(gb+h*2+1);
        acc0 += 1.f - __fdividef(2.f, __expf(2.f*z0)+1.f);
        acc1 += 1.f - __fdividef(2.f, __expf(2.f*z1)+1.f);
      }
    }
    acc0 *= 0.125f; acc1 *= 0.125f;

    float xi0 = xsa[i*12+t], xi1 = xsa[NV*12 + i*12+t];
    long obase = (long)(b*NV + i)*768;
    #pragma unroll
    for (int r=0;r<2;r++){
      int e = lane + r*32;
      g_out[obase + e*12 + t] = xi0*w1s[e] + xi1*w1s[64+e]
                              + acc0*w1s[128+e] + acc1*w1s[192+e] + b1s[e];
    }
  }
}

// 2-column GEMM: columns c0, c1 far apart; 12 tokens in 6 f32x2 accumulators.
__device__ __forceinline__ void gemm2(const float* __restrict__ sIn,
                                      const float* __restrict__ W, int ldw,
                                      int c0, int c1, int k0, int nk,
                                      u64t A[6], u64t Bc[6]){
  #pragma unroll 4
  for (int k=k0; k<k0+nk; k++){
    const float* wr = W + (long)k*ldw;
    u64t wa = pack2(__ldg(wr+c0));
    u64t wb = pack2(__ldg(wr+c1));
    const ulonglong2* a = (const ulonglong2*)(sIn + k*ST);
    ulonglong2 v0 = a[0], v1 = a[1], v2 = a[2];
    fma2(A[0], v0.x, wa); fma2(Bc[0], v0.x, wb);
    fma2(A[1], v0.y, wa); fma2(Bc[1], v0.y, wb);
    fma2(A[2], v1.x, wa); fma2(Bc[2], v1.x, wb);
    fma2(A[3], v1.y, wa); fma2(Bc[3], v1.y, wb);
    fma2(A[4], v2.x, wa); fma2(Bc[4], v2.x, wb);
    fma2(A[5], v2.y, wa); fma2(Bc[5], v2.y, wb);
  }
}

__device__ __forceinline__ void store6(float* dst, const u64t A[6]){
  #pragma unroll
  for (int p=0;p<6;p++) ((float2*)dst)[p] = *(const float2*)&A[p];
}

// ---------------------------------------------------------------------------
// K2: BOTH transformer layers + conv2/conv3 head fused.
// grid 1656 (=B*N), block 256. smem arena 46KB.
// ---------------------------------------------------------------------------
#define S_QQ 0
#define S_Q  1280
#define S_K  2560
#define S_V  3840
#define S_X1 5120
#define S_H  6400      // 5120 floats
#define SM_TOT 11520

__global__ void __launch_bounds__(256, 4) k_fused(
    const float* __restrict__ temb,
    const float* __restrict__ Wq, const float* __restrict__ Wk,
    const float* __restrict__ Wv, const float* __restrict__ Wo,
    const float* __restrict__ bo,
    const float* __restrict__ ln1g, const float* __restrict__ ln1b,
    const float* __restrict__ ln2g, const float* __restrict__ ln2b,
    const float* __restrict__ fw1, const float* __restrict__ fb1,
    const float* __restrict__ fw2, const float* __restrict__ fb2,
    const float* __restrict__ lng, const float* __restrict__ lnb,
    const float* __restrict__ w2c, const float* __restrict__ b2c,
    const float* __restrict__ w3c, const float* __restrict__ b3c,
    float* __restrict__ outp)
{
  __shared__ __align__(16) float sm[SM_TOT];

  int tid = threadIdx.x;
  int warp = tid>>5, lane = tid&31;
  long base = (long)blockIdx.x * 768;

  for (int idx=tid; idx<768; idx+=256){
    int e = idx/12, t = idx - e*12;
    sm[S_QQ + e*ST+t] = g_out[base+idx] + __ldg(temb + t*64+e);
  }
  __syncthreads();

  for (int l=0; l<LL; l++){
    const float* Wq_  = Wq  + l*4096;
    const float* Wk_  = Wk  + l*4096;
    const float* Wv_  = Wv  + l*4096;
    const float* Wo_  = Wo  + l*4096;
    const float* bo_  = bo  + l*64;
    const float* ln1g_= ln1g+ l*64;  const float* ln1b_= ln1b+ l*64;
    const float* ln2g_= ln2g+ l*64;  const float* ln2b_= ln2b+ l*64;
    const float* fw1_ = fw1 + l*16384; const float* fb1_ = fb1 + l*256;
    const float* fw2_ = fw2 + l*16384; const float* fb2_ = fb2 + l*64;
    const float* lng_ = lng + l*64;  const float* lnb_ = lnb + l*64;

    // ---- Q,K,V split-k: 192 threads = 3 mats x (32 e2 x 2 kgroups) ----
    // partial buffer m*2+kg: 0..4 in S_H, 5 in S_X1. Layout [e][PT].
    if (tid < 192){
      int m  = tid >> 6;           // 0,1,2
      int kg = (tid >> 5) & 1;
      int e2 = tid & 31;
      const float* W = (m==0 ? Wq_ : (m==1 ? Wk_ : Wv_));
      int bi = m*2 + kg;
      float* pb = (bi < 5) ? (sm + S_H + bi*896) : (sm + S_X1);
      u64t A[6]={0,0,0,0,0,0}, B[6]={0,0,0,0,0,0};
      gemm2(sm + S_QQ, W, 64, e2, e2+32, kg*32, 32, A, B);
      store6(pb + e2*PT, A);
      store6(pb + (e2+32)*PT, B);
    }
    __syncthreads();
    // sum partials -> Q,K,V
    for (int idx=tid; idx<2304; idx+=256){
      int m = idx/768, r = idx - m*768;
      int e = r/12, t = r - e*12;
      const float* p0 = (m*2   < 5) ? (sm + S_H + (m*2  )*896) : (sm + S_X1);
      const float* p1 = (m*2+1 < 5) ? (sm + S_H + (m*2+1)*896) : (sm + S_X1);
      float v = p0[e*PT+t] + p1[e*PT+t];
      float* dst = sm + (m==0 ? S_Q : (m==1 ? S_K : S_V));
      dst[e*ST+t] = v;
    }
    __syncthreads();

    // ---- attention scores (into S_H; partials dead) ----
    for (int idx=tid; idx<576; idx+=256){
      int h = idx/144, rem = idx - h*144;
      int t2 = rem/12, s = rem - t2*12;
      const float* qp = sm + S_Q + (h*16)*ST + t2;
      const float* kp = sm + S_K + (h*16)*ST + s;
      float sum=0.f;
      #pragma unroll
      for (int dd=0;dd<16;dd++) sum += qp[dd*ST]*kp[dd*ST];
      sm[S_H + idx] = sum*0.25f;
    }
    __syncthreads();
    if (tid < 48){
      float* row = sm + S_H + tid*12;
      float mxv = row[0];
      #pragma unroll
      for (int s=1;s<12;s++) mxv = fmaxf(mxv,row[s]);
      float evv[12]; float sum=0.f;
      #pragma unroll
      for (int s=0;s<12;s++){ evv[s]=__expf(row[s]-mxv); sum+=evv[s]; }
      float inv = 1.f/sum;
      #pragma unroll
      for (int s=0;s<12;s++) row[s]=evv[s]*inv;
    }
    __syncthreads();

    // ---- ctx = att @ V (into S_Q; Q dead) ----
    for (int idx=tid; idx<768; idx+=256){
      int e = idx/12, t2 = idx - e*12, h = e>>4;
      const float* a = sm + S_H + (h*12+t2)*12;
      const float* vp = sm + S_V + e*ST;
      float sum=0.f;
      #pragma unroll
      for (int s=0;s<12;s++) sum += a[s]*vp[s];
      sm[S_Q + e*ST+t2] = sum;
    }
    __syncthreads();

    // ---- attn_out = ctx @ Wo : 128 threads, 4 kgroups; partials -> S_H ----
    if (tid < 128){
      int kg = tid>>5, e2 = tid&31;
      u64t A[6]={0,0,0,0,0,0}, B[6]={0,0,0,0,0,0};
      gemm2(sm + S_Q, Wo_, 64, e2, e2+32, kg*16, 16, A, B);
      float* pb = sm + S_H + kg*896;
      store6(pb + e2*PT, A);
      store6(pb + (e2+32)*PT, B);
    }
    __syncthreads();

    // ---- LN1 merged with Wo-sum + bias + residual; -> S_X1 ----
    for (int t = warp; t < 12; t += 8){
      int e0 = lane, e1 = lane+32;
      float v0 = sm[S_H+e0*PT+t]+sm[S_H+896+e0*PT+t]+sm[S_H+1792+e0*PT+t]+sm[S_H+2688+e0*PT+t]
               + bo_[e0] + sm[S_QQ+e0*ST+t];
      float v1 = sm[S_H+e1*PT+t]+sm[S_H+896+e1*PT+t]+sm[S_H+1792+e1*PT+t]+sm[S_H+2688+e1*PT+t]
               + bo_[e1] + sm[S_QQ+e1*ST+t];
      float s  = warp_sum(v0+v1);
      float s2 = warp_sum(v0*v0+v1*v1);
      float mean = s*(1.f/64.f);
      float var  = s2*(1.f/64.f) - mean*mean;
      float r = rsqrtf(var + 1e-5f);
      sm[S_X1+e0*ST+t] = (v0-mean)*r*ln1g_[e0] + ln1b_[e0];
      sm[S_X1+e1*ST+t] = (v1-mean)*r*ln1g_[e1] + ln1b_[e1];
    }
    __syncthreads();

    // ---- FF1: 128 threads, cols (f, f+128), k=64; relu -> S_H ----
    if (tid < 128){
      int f = tid;
      u64t A[6]={0,0,0,0,0,0}, B[6]={0,0,0,0,0,0};
      gemm2(sm + S_X1, fw1_, 256, f, f+128, 0, 64, A, B);
      float ba = fb1_[f], bb2 = fb1_[f+128];
      float* dA = sm + S_H + f*ST;
      float* dB = sm + S_H + (f+128)*ST;
      #pragma unroll
      for (int p=0;p<6;p++){
        float2 va = *(const float2*)&A[p];
        float2 vb = *(const float2*)&B[p];
        va.x = fmaxf(va.x+ba,0.f);  va.y = fmaxf(va.y+ba,0.f);
        vb.x = fmaxf(vb.x+bb2,0.f); vb.y = fmaxf(vb.y+bb2,0.f);
        ((float2*)dA)[p] = va;
        ((float2*)dB)[p] = vb;
      }
    }
    __syncthreads();

    // ---- FF2: 128 threads, 4 kgroups of 64; partials -> S_Q region ----
    if (tid < 128){
      int kg = tid>>5, e2 = tid&31;
      u64t A[6]={0,0,0,0,0,0}, B[6]={0,0,0,0,0,0};
      gemm2(sm + S_H, fw2_, 64, e2, e2+32, kg*64, 64, A, B);
      float* pb = sm + S_Q + kg*896;
      store6(pb + e2*PT, A);
      store6(pb + (e2+32)*PT, B);
    }
    __syncthreads();

    // ---- LN2 merged with FF2-sum + bias + residual(X1); -> S_X1 ----
    for (int t = warp; t < 12; t += 8){
      int e0 = lane, e1 = lane+32;
      float v0 = sm[S_Q+e0*PT+t]+sm[S_Q+896+e0*PT+t]+sm[S_Q+1792+e0*PT+t]+sm[S_Q+2688+e0*PT+t]
               + fb2_[e0] + sm[S_X1+e0*ST+t];
      float v1 = sm[S_Q+e1*PT+t]+sm[S_Q+896+e1*PT+t]+sm[S_Q+1792+e1*PT+t]+sm[S_Q+2688+e1*PT+t]
               + fb2_[e1] + sm[S_X1+e1*ST+t];
      float s  = warp_sum(v0+v1);
      float s2 = warp_sum(v0*v0+v1*v1);
      float mean = s*(1.f/64.f);
      float var  = s2*(1.f/64.f) - mean*mean;
      float r = rsqrtf(var + 1e-5f);
      sm[S_X1+e0*ST+t] = (v0-mean)*r*ln2g_[e0] + ln2b_[e0];
      sm[S_X1+e1*ST+t] = (v1-mean)*r*ln2g_[e1] + ln2b_[e1];
    }
    __syncthreads();

    // ---- LN3 merged with residual (QQ - temb); writes QQ(+temb) or S_K ----
    for (int t = warp; t < 12; t += 8){
      int e0 = lane, e1 = lane+32;
      float te0 = __ldg(temb + t*64+e0), te1 = __ldg(temb + t*64+e1);
      float v0 = sm[S_X1+e0*ST+t] + sm[S_QQ+e0*ST+t] - te0;
      float v1 = sm[S_X1+e1*ST+t] + sm[S_QQ+e1*ST+t] - te1;
      float s  = warp_sum(v0+v1);
      float s2 = warp_sum(v0*v0+v1*v1);
      float mean = s*(1.f/64.f);
      float var  = s2*(1.f/64.f) - mean*mean;
      float r = rsqrtf(var + 1e-5f);
      float o0 = (v0-mean)*r*lng_[e0] + lnb_[e0];
      float o1 = (v1-mean)*r*lng_[e1] + lnb_[e1];
      if (l+1 < LL){
        sm[S_QQ+e0*ST+t] = o0 + te0;
        sm[S_QQ+e1*ST+t] = o1 + te1;
      } else {
        sm[S_K+e0*ST+t] = o0;
        sm[S_K+e1*ST+t] = o1;
      }
    }
    __syncthreads();
  }

  // ---- head: conv2 over t (relu) + conv3 over e. out in S_K ----
  if (tid < 192){
    int o = tid>>4, es = (tid&15)*4;
    float w2row[12];
    #pragma unroll
    for (int t=0;t<12;t++) w2row[t] = __ldg(w2c + o*12 + t);
    float b2v = __ldg(b2c + o);
    float acc = 0.f;
    #pragma unroll
    for (int q=0;q<4;q++){
      int e = es + q;
      const float* rowp = sm + S_K + e*ST;
      float v = b2v;
      #pragma unroll
      for (int t=0;t<12;t++) v += rowp[t]*w2row[t];
      v = fmaxf(v, 0.f);
      acc += v * __ldg(w3c + e);
    }
    #pragma unroll
    for (int off=8; off; off>>=1) acc += __shfl_xor_sync(0xffffffffu, acc, off);
    if ((tid&15)==0) outp[(long)blockIdx.x*12 + o] = acc + __ldg(b3c);
  }
}

// ---------------------------------------------------------------------------
extern "C" void kernel_launch(void* const* d_in, const int* in_sizes, int n_in,
                              void* d_out, int out_size) {
  const float* x       = (const float*)d_in[0];
  const int*   adj     = (const int*)  d_in[1];
  const float* gat_W2  = (const float*)d_in[2];
  const float* gat_a   = (const float*)d_in[3];
  const float* gat_b   = (const float*)d_in[4];
  const float* conv1_w = (const float*)d_in[5];
  const float* conv1_b = (const float*)d_in[6];
  const float* temb    = (const float*)d_in[7];
  const float* Wq      = (const float*)d_in[8];
  const float* Wk      = (const float*)d_in[9];
  const float* Wv      = (const float*)d_in[10];
  const float* Wo      = (const float*)d_in[11];
  const float* bo      = (const float*)d_in[12];
  const float* ln1_g   = (const float*)d_in[13];
  const float* ln1_b   = (const float*)d_in[14];
  const float* ln2_g   = (const float*)d_in[15];
  const float* ln2_b   = (const float*)d_in[16];
  const float* ff_w1   = (const float*)d_in[17];
  const float* ff_b1   = (const float*)d_in[18];
  const float* ff_w2   = (const float*)d_in[19];
  const float* ff_b2   = (const float*)d_in[20];
  const float* lng     = (const float*)d_in[21];
  const float* lnb     = (const float*)d_in[22];
  const float* conv2_w = (const float*)d_in[23];
  const float* conv2_b = (const float*)d_in[24];
  const float* conv3_w = (const float*)d_in[25];
  const float* conv3_b = (const float*)d_in[26];
  float* outp = (float*)d_out;

  dim3 g1(BB, (NV + 1) / 2);
  k_gat<<<g1, 128>>>(x, adj, gat_W2, gat_a, gat_b, conv1_w, conv1_b);

  k_fused<<<BB*NV, 256>>>(temb, Wq, Wk, Wv, Wo, bo,
                          ln1_g, ln1_b, ln2_g, ln2_b,
                          ff_w1, ff_b1, ff_w2, ff_b2,
                          lng, lnb,
                          conv2_w, conv2_b, conv3_w, conv3_b, outp);
}

// round 8
// speedup vs baseline: 1.3618x; 1.0269x over previous
#include <cuda_runtime.h>

#define BB 8
#define NV 207
#define TT 12
#define LL 2
#define NGH 8
#define ALPHA 0.2f
#define NN (NV*NV)
#define ST 20   // k-major stride for activation buffers (floats)
#define PT 14   // stride for partial-sum buffers
#define XR 418  // xsa row stride (per t), not a multiple of 32

typedef unsigned long long u64t;

// scratch: gat output (B*N groups, layout per group: e*12+t)
__device__ float g_out[BB*NV*TT*64];

__device__ __forceinline__ float warp_sum(float v){
  #pragma unroll
  for (int o=16;o;o>>=1) v += __shfl_xor_sync(0xffffffffu, v, o);
  return v;
}
__device__ __forceinline__ u64t pack2(float v){
  u64t r; asm("mov.b64 %0, {%1, %1};" : "=l"(r) : "f"(v)); return r;
}
__device__ __forceinline__ void fma2(u64t &acc, u64t a, u64t b){
  asm("fma.rn.f32x2 %0, %1, %2, %0;" : "+l"(acc) : "l"(a), "l"(b));
}

// ---------------------------------------------------------------------------
// K1: GAT + conv1. Block = (b, 2-row chunk). x[b] staged TRANSPOSED [t][2n+c].
// ---------------------------------------------------------------------------
__global__ void __launch_bounds__(128) k_gat(
    const float* __restrict__ x,      // (B,C,N,T)
    const int*   __restrict__ adj,    // (B,N,N)
    const float* __restrict__ W2,     // (8,4,2)
    const float* __restrict__ ga,     // (8,2)
    const float* __restrict__ gb,     // (8,2)
    const float* __restrict__ w1,     // (4,64)
    const float* __restrict__ b1)     // (64)
{
  __shared__ float xsa[TT*XR];     // [t][2n+c]
  __shared__ int   adjs[2*NV];
  __shared__ float w1s[256];
  __shared__ float b1s[64];

  int b  = blockIdx.x;
  int i0 = blockIdx.y * 2;
  int tid = threadIdx.x;

  const float* xb = x + (long)b*2*NV*TT;
  for (int idx=tid; idx<2*NV*TT; idx+=128){
    int c = idx/(NV*TT); int r = idx - c*NV*TT;
    int n = r/TT, t = r - n*TT;
    xsa[t*XR + 2*n + c] = xb[idx];
  }
  int nrows = (NV - i0) < 2 ? (NV - i0) : 2;
  for (int idx=tid; idx<nrows*NV; idx+=128){
    int ii = idx / NV, j = idx - ii*NV;
    adjs[ii*NV+j] = adj[((long)b*NV + i0+ii)*NV + j];
  }
  for (int idx=tid; idx<256; idx+=128) w1s[idx]=w1[idx];
  if (tid<64) b1s[tid]=b1[tid];
  __syncthreads();

  int warp = tid>>5, lane = tid&31;

  for (int task = warp; task < 24; task += 4){
    int t  = task % 12;
    int ii = task / 12;
    int i  = i0 + ii;
    if (i >= NV) continue;
    const int* arow = adjs + ii*NV;
    const float* xrow = xsa + t*XR;

    float acc0=0.f, acc1=0.f;
    #pragma unroll
    for (int hg=0; hg<2; hg++){
      float w2r[4][4][2], ar[4][2];
      #pragma unroll
      for (int hh=0;hh<4;hh++){
        int h = hg*4+hh;
        #pragma unroll
        for (int k=0;k<4;k++){
          w2r[hh][k][0]=__ldg(W2+(h*4+k)*2+0);
          w2r[hh][k][1]=__ldg(W2+(h*4+k)*2+1);
        }
        ar[hh][0]=__ldg(ga+h*2); ar[hh][1]=__ldg(ga+h*2+1);
      }
      float d[4]={0,0,0,0}, n0[4]={0,0,0,0}, n1[4]={0,0,0,0};
      #pragma unroll
      for (int jj=0; jj<7; jj++){
        int j = jj*32 + lane;
        bool valid = j < NV;
        int jc = valid ? j : 0;
        bool ok = valid && (arow[jc] > 0);
        int r0 = 2*(i*NV + jc);
        int r1 = r0 + 1;
        int a0 = (r0 < NN) ? (r0 / NV) : ((r0 - NN) % NV);
        int a1 = (r1 < NN) ? (r1 / NV) : ((r1 - NN) % NV);
        float2 ca = *(const float2*)(xrow + 2*a0);
        float2 cb = *(const float2*)(xrow + 2*a1);
        float2 xj = *(const float2*)(xrow + 2*jc);
        #pragma unroll
        for (int hh=0;hh<4;hh++){
          float we0 = ca.x*w2r[hh][0][0] + ca.y*w2r[hh][1][0] + cb.x*w2r[hh][2][0] + cb.y*w2r[hh][3][0];
          float we1 = ca.x*w2r[hh][0][1] + ca.y*w2r[hh][1][1] + cb.x*w2r[hh][2][1] + cb.y*w2r[hh][3][1];
          we0 = (we0 > 0.f) ? we0 : ALPHA*we0;
          we1 = (we1 > 0.f) ? we1 : ALPHA*we1;
          float e = we0*ar[hh][0] + we1*ar[hh][1];
          float w = ok ? __expf(e) : 0.f;
          d[hh]  += w;
          n0[hh] += w*xj.x;
          n1[hh] += w*xj.y;
        }
      }
      #pragma unroll
      for (int off=16; off; off>>=1){
        #pragma unroll
        for (int hh=0;hh<4;hh++){
          d[hh]  += __shfl_xor_sync(0xffffffffu, d[hh],  off);
          n0[hh] += __shfl_xor_sync(0xffffffffu, n0[hh], off);
          n1[hh] += __shfl_xor_sync(0xffffffffu, n1[hh], off);
        }
      }
      #pragma unroll
      for (int hh=0;hh<4;hh++){
        int h = hg*4+hh;
        float inv = 1.0f/d[hh];
        float z0 = n0[hh]*inv + __ldg(gb+h*2+0);
        float z1 = n1[hh]*inv + __ldg(gb+h*2+1);
        acc0 += 1.f - __fdividef(2.f, __expf(2.f*z0)+1.f);
        acc1 += 1.f - __fdividef(2.f, __expf(2.f*z1)+1.f);
      }
    }
    acc0 *= 0.125f; acc1 *= 0.125f;

    float xi0 = xrow[2*i], xi1 = xrow[2*i+1];
    long obase = (long)(b*NV + i)*768;
    #pragma unroll
    for (int r=0;r<2;r++){
      int e = lane + r*32;
      g_out[obase + e*12 + t] = xi0*w1s[e] + xi1*w1s[64+e]
                              + acc0*w1s[128+e] + acc1*w1s[192+e] + b1s[e];
    }
  }
}

// 2-column GEMM: columns c0, c1 far apart; 12 tokens in 6 f32x2 accumulators.
__device__ __forceinline__ void gemm2(const float* __restrict__ sIn,
                                      const float* __restrict__ W, int ldw,
                                      int c0, int c1, int k0, int nk,
                                      u64t A[6], u64t Bc[6]){
  #pragma unroll 4
  for (int k=k0; k<k0+nk; k++){
    const float* wr = W + (long)k*ldw;
    u64t wa = pack2(__ldg(wr+c0));
    u64t wb = pack2(__ldg(wr+c1));
    const ulonglong2* a = (const ulonglong2*)(sIn + k*ST);
    ulonglong2 v0 = a[0], v1 = a[1], v2 = a[2];
    fma2(A[0], v0.x, wa); fma2(Bc[0], v0.x, wb);
    fma2(A[1], v0.y, wa); fma2(Bc[1], v0.y, wb);
    fma2(A[2], v1.x, wa); fma2(Bc[2], v1.x, wb);
    fma2(A[3], v1.y, wa); fma2(Bc[3], v1.y, wb);
    fma2(A[4], v2.x, wa); fma2(Bc[4], v2.x, wb);
    fma2(A[5], v2.y, wa); fma2(Bc[5], v2.y, wb);
  }
}

__device__ __forceinline__ void store6(float* dst, const u64t A[6]){
  #pragma unroll
  for (int p=0;p<6;p++) ((float2*)dst)[p] = *(const float2*)&A[p];
}

// ---------------------------------------------------------------------------
// K2: BOTH transformer layers + conv2/conv3 head fused.
// grid 1656 (=B*N), block 256. smem arena 46KB.
// ---------------------------------------------------------------------------
#define S_QQ 0
#define S_Q  1280
#define S_K  2560
#define S_V  3840
#define S_X1 5120
#define S_H  6400      // 5120 floats
#define SM_TOT 11520

__global__ void __launch_bounds__(256, 4) k_fused(
    const float* __restrict__ temb,
    const float* __restrict__ Wq, const float* __restrict__ Wk,
    const float* __restrict__ Wv, const float* __restrict__ Wo,
    const float* __restrict__ bo,
    const float* __restrict__ ln1g, const float* __restrict__ ln1b,
    const float* __restrict__ ln2g, const float* __restrict__ ln2b,
    const float* __restrict__ fw1, const float* __restrict__ fb1,
    const float* __restrict__ fw2, const float* __restrict__ fb2,
    const float* __restrict__ lng, const float* __restrict__ lnb,
    const float* __restrict__ w2c, const float* __restrict__ b2c,
    const float* __restrict__ w3c, const float* __restrict__ b3c,
    float* __restrict__ outp)
{
  __shared__ __align__(16) float sm[SM_TOT];

  int tid = threadIdx.x;
  int warp = tid>>5, lane = tid&31;
  long base = (long)blockIdx.x * 768;

  for (int idx=tid; idx<768; idx+=256){
    int e = idx/12, t = idx - e*12;
    sm[S_QQ + e*ST+t] = g_out[base+idx] + __ldg(temb + t*64+e);
  }
  __syncthreads();

  for (int l=0; l<LL; l++){
    const float* Wq_  = Wq  + l*4096;
    const float* Wk_  = Wk  + l*4096;
    const float* Wv_  = Wv  + l*4096;
    const float* Wo_  = Wo  + l*4096;
    const float* bo_  = bo  + l*64;
    const float* ln1g_= ln1g+ l*64;  const float* ln1b_= ln1b+ l*64;
    const float* ln2g_= ln2g+ l*64;  const float* ln2b_= ln2b+ l*64;
    const float* fw1_ = fw1 + l*16384; const float* fb1_ = fb1 + l*256;
    const float* fw2_ = fw2 + l*16384; const float* fb2_ = fb2 + l*64;
    const float* lng_ = lng + l*64;  const float* lnb_ = lnb + l*64;

    // ---- Q,K,V split-k: 192 threads = 3 mats x (32 e2 x 2 kgroups) ----
    if (tid < 192){
      int m  = tid >> 6;
      int kg = (tid >> 5) & 1;
      int e2 = tid & 31;
      const float* W = (m==0 ? Wq_ : (m==1 ? Wk_ : Wv_));
      int bi = m*2 + kg;
      float* pb = (bi < 5) ? (sm + S_H + bi*896) : (sm + S_X1);
      u64t A[6]={0,0,0,0,0,0}, B[6]={0,0,0,0,0,0};
      gemm2(sm + S_QQ, W, 64, e2, e2+32, kg*32, 32, A, B);
      store6(pb + e2*PT, A);
      store6(pb + (e2+32)*PT, B);
    }
    __syncthreads();
    // sum partials -> Q,K,V
    for (int idx=tid; idx<2304; idx+=256){
      int m = idx/768, r = idx - m*768;
      int e = r/12, t = r - e*12;
      const float* p0 = (m*2   < 5) ? (sm + S_H + (m*2  )*896) : (sm + S_X1);
      const float* p1 = (m*2+1 < 5) ? (sm + S_H + (m*2+1)*896) : (sm + S_X1);
      float v = p0[e*PT+t] + p1[e*PT+t];
      float* dst = sm + (m==0 ? S_Q : (m==1 ? S_K : S_V));
      dst[e*ST+t] = v;
    }
    __syncthreads();

    // ---- attention scores: 192 threads, 3 scores each; q row in regs ----
    if (tid < 192){
      int h = tid / 48;
      int rem = tid - h*48;
      int t2 = rem >> 2;
      int sq = (rem & 3) * 3;
      const float* qp = sm + S_Q + (h*16)*ST + t2;
      float q[16];
      #pragma unroll
      for (int d=0; d<16; d++) q[d] = qp[d*ST];
      #pragma unroll
      for (int j=0;j<3;j++){
        int s = sq + j;
        const float* kp = sm + S_K + (h*16)*ST + s;
        float sum=0.f;
        #pragma unroll
        for (int d=0;d<16;d++) sum += q[d]*kp[d*ST];
        sm[S_H + (h*12+t2)*12 + s] = sum*0.25f;
      }
    }
    __syncthreads();
    if (tid < 48){
      float* row = sm + S_H + tid*12;
      float mxv = row[0];
      #pragma unroll
      for (int s=1;s<12;s++) mxv = fmaxf(mxv,row[s]);
      float evv[12]; float sum=0.f;
      #pragma unroll
      for (int s=0;s<12;s++){ evv[s]=__expf(row[s]-mxv); sum+=evv[s]; }
      float inv = 1.f/sum;
      #pragma unroll
      for (int s=0;s<12;s++) row[s]=evv[s]*inv;
    }
    __syncthreads();

    // ---- ctx = att @ V (float4 loads; into S_Q) ----
    for (int idx=tid; idx<768; idx+=256){
      int e = idx/12, t2 = idx - e*12, h = e>>4;
      const float4* a4 = (const float4*)(sm + S_H + (h*12+t2)*12);
      const float4* v4 = (const float4*)(sm + S_V + e*ST);
      float4 a0=a4[0], a1=a4[1], a2=a4[2];
      float4 v0=v4[0], v1=v4[1], v2=v4[2];
      float sum = a0.x*v0.x + a0.y*v0.y + a0.z*v0.z + a0.w*v0.w
                + a1.x*v1.x + a1.y*v1.y + a1.z*v1.z + a1.w*v1.w
                + a2.x*v2.x + a2.y*v2.y + a2.z*v2.z + a2.w*v2.w;
      sm[S_Q + e*ST+t2] = sum;
    }
    __syncthreads();

    // ---- attn_out = ctx @ Wo : 128 threads, 4 kgroups; partials -> S_H ----
    if (tid < 128){
      int kg = tid>>5, e2 = tid&31;
      u64t A[6]={0,0,0,0,0,0}, B[6]={0,0,0,0,0,0};
      gemm2(sm + S_Q, Wo_, 64, e2, e2+32, kg*16, 16, A, B);
      float* pb = sm + S_H + kg*896;
      store6(pb + e2*PT, A);
      store6(pb + (e2+32)*PT, B);
    }
    __syncthreads();

    // ---- LN1 merged with Wo-sum + bias + residual; -> S_X1 ----
    for (int t = warp; t < 12; t += 8){
      int e0 = lane, e1 = lane+32;
      float v0 = sm[S_H+e0*PT+t]+sm[S_H+896+e0*PT+t]+sm[S_H+1792+e0*PT+t]+sm[S_H+2688+e0*PT+t]
               + bo_[e0] + sm[S_QQ+e0*ST+t];
      float v1 = sm[S_H+e1*PT+t]+sm[S_H+896+e1*PT+t]+sm[S_H+1792+e1*PT+t]+sm[S_H+2688+e1*PT+t]
               + bo_[e1] + sm[S_QQ+e1*ST+t];
      float s  = warp_sum(v0+v1);
      float s2 = warp_sum(v0*v0+v1*v1);
      float mean = s*(1.f/64.f);
      float var  = s2*(1.f/64.f) - mean*mean;
      float r = rsqrtf(var + 1e-5f);
      sm[S_X1+e0*ST+t] = (v0-mean)*r*ln1g_[e0] + ln1b_[e0];
      sm[S_X1+e1*ST+t] = (v1-mean)*r*ln1g_[e1] + ln1b_[e1];
    }
    __syncthreads();

    // ---- FF1: 128 threads, cols (f, f+128), k=64; relu -> S_H ----
    if (tid < 128){
      int f = tid;
      u64t A[6]={0,0,0,0,0,0}, B[6]={0,0,0,0,0,0};
      gemm2(sm + S_X1, fw1_, 256, f, f+128, 0, 64, A, B);
      float ba = fb1_[f], bb2 = fb1_[f+128];
      float* dA = sm + S_H + f*ST;
      float* dB = sm + S_H + (f+128)*ST;
      #pragma unroll
      for (int p=0;p<6;p++){
        float2 va = *(const float2*)&A[p];
        float2 vb = *(const float2*)&B[p];
        va.x = fmaxf(va.x+ba,0.f);  va.y = fmaxf(va.y+ba,0.f);
        vb.x = fmaxf(vb.x+bb2,0.f); vb.y = fmaxf(vb.y+bb2,0.f);
        ((float2*)dA)[p] = va;
        ((float2*)dB)[p] = vb;
      }
    }
    __syncthreads();

    // ---- FF2: 128 threads, 4 kgroups of 64; partials -> S_Q region ----
    if (tid < 128){
      int kg = tid>>5, e2 = tid&31;
      u64t A[6]={0,0,0,0,0,0}, B[6]={0,0,0,0,0,0};
      gemm2(sm + S_H, fw2_, 64, e2, e2+32, kg*64, 64, A, B);
      float* pb = sm + S_Q + kg*896;
      store6(pb + e2*PT, A);
      store6(pb + (e2+32)*PT, B);
    }
    __syncthreads();

    // ---- LN2 merged with FF2-sum + bias + residual(X1); -> S_X1 ----
    for (int t = warp; t < 12; t += 8){
      int e0 = lane, e1 = lane+32;
      float v0 = sm[S_Q+e0*PT+t]+sm[S_Q+896+e0*PT+t]+sm[S_Q+1792+e0*PT+t]+sm[S_Q+2688+e0*PT+t]
               + fb2_[e0] + sm[S_X1+e0*ST+t];
      float v1 = sm[S_Q+e1*PT+t]+sm[S_Q+896+e1*PT+t]+sm[S_Q+1792+e1*PT+t]+sm[S_Q+2688+e1*PT+t]
               + fb2_[e1] + sm[S_X1+e1*ST+t];
      float s  = warp_sum(v0+v1);
      float s2 = warp_sum(v0*v0+v1*v1);
      float mean = s*(1.f/64.f);
      float var  = s2*(1.f/64.f) - mean*mean;
      float r = rsqrtf(var + 1e-5f);
      sm[S_X1+e0*ST+t] = (v0-mean)*r*ln2g_[e0] + ln2b_[e0];
      sm[S_X1+e1*ST+t] = (v1-mean)*r*ln2g_[e1] + ln2b_[e1];
    }
    __syncthreads();

    // ---- LN3 merged with residual (QQ - temb) ----
    for (int t = warp; t < 12; t += 8){
      int e0 = lane, e1 = lane+32;
      float te0 = __ldg(temb + t*64+e0), te1 = __ldg(temb + t*64+e1);
      float v0 = sm[S_X1+e0*ST+t] + sm[S_QQ+e0*ST+t] - te0;
      float v1 = sm[S_X1+e1*ST+t] + sm[S_QQ+e1*ST+t] - te1;
      float s  = warp_sum(v0+v1);
      float s2 = warp_sum(v0*v0+v1*v1);
      float mean = s*(1.f/64.f);
      float var  = s2*(1.f/64.f) - mean*mean;
      float r = rsqrtf(var + 1e-5f);
      float o0 = (v0-mean)*r*lng_[e0] + lnb_[e0];
      float o1 = (v1-mean)*r*lng_[e1] + lnb_[e1];
      if (l+1 < LL){
        sm[S_QQ+e0*ST+t] = o0 + te0;
        sm[S_QQ+e1*ST+t] = o1 + te1;
      } else {
        sm[S_K+e0*ST+t] = o0;
        sm[S_K+e1*ST+t] = o1;
      }
    }
    __syncthreads();
  }

  // ---- head: conv2 over t (relu) + conv3 over e. out in S_K ----
  if (tid < 192){
    int o = tid>>4, es = (tid&15)*4;
    float w2row[12];
    #pragma unroll
    for (int t=0;t<12;t++) w2row[t] = __ldg(w2c + o*12 + t);
    float b2v = __ldg(b2c + o);
    float acc = 0.f;
    #pragma unroll
    for (int q=0;q<4;q++){
      int e = es + q;
      const float* rowp = sm + S_K + e*ST;
      float v = b2v;
      #pragma unroll
      for (int t=0;t<12;t++) v += rowp[t]*w2row[t];
      v = fmaxf(v, 0.f);
      acc += v * __ldg(w3c + e);
    }
    #pragma unroll
    for (int off=8; off; off>>=1) acc += __shfl_xor_sync(0xffffffffu, acc, off);
    if ((tid&15)==0) outp[(long)blockIdx.x*12 + o] = acc + __ldg(b3c);
  }
}

// ---------------------------------------------------------------------------
extern "C" void kernel_launch(void* const* d_in, const int* in_sizes, int n_in,
                              void* d_out, int out_size) {
  const float* x       = (const float*)d_in[0];
  const int*   adj     = (const int*)  d_in[1];
  const float* gat_W2  = (const float*)d_in[2];
  const float* gat_a   = (const float*)d_in[3];
  const float* gat_b   = (const float*)d_in[4];
  const float* conv1_w = (const float*)d_in[5];
  const float* conv1_b = (const float*)d_in[6];
  const float* temb    = (const float*)d_in[7];
  const float* Wq      = (const float*)d_in[8];
  const float* Wk      = (const float*)d_in[9];
  const float* Wv      = (const float*)d_in[10];
  const float* Wo      = (const float*)d_in[11];
  const float* bo      = (const float*)d_in[12];
  const float* ln1_g   = (const float*)d_in[13];
  const float* ln1_b   = (const float*)d_in[14];
  const float* ln2_g   = (const float*)d_in[15];
  const float* ln2_b   = (const float*)d_in[16];
  const float* ff_w1   = (const float*)d_in[17];
  const float* ff_b1   = (const float*)d_in[18];
  const float* ff_w2   = (const float*)d_in[19];
  const float* ff_b2   = (const float*)d_in[20];
  const float* lng     = (const float*)d_in[21];
  const float* lnb     = (const float*)d_in[22];
  const float* conv2_w = (const float*)d_in[23];
  const float* conv2_b = (const float*)d_in[24];
  const float* conv3_w = (const float*)d_in[25];
  const float* conv3_b = (const float*)d_in[26];
  float* outp = (float*)d_out;

  dim3 g1(BB, (NV + 1) / 2);
  k_gat<<<g1, 128>>>(x, adj, gat_W2, gat_a, gat_b, conv1_w, conv1_b);

  k_fused<<<BB*NV, 256>>>(temb, Wq, Wk, Wv, Wo, bo,
                          ln1_g, ln1_b, ln2_g, ln2_b,
                          ff_w1, ff_b1, ff_w2, ff_b2,
                          lng, lnb,
                          conv2_w, conv2_b, conv3_w, conv3_b, outp);
}